// round 6
// baseline (speedup 1.0000x reference)
#include <cuda_runtime.h>

// Problem sizes (fixed by the reference)
#define Nn   20000
#define Ee   320000
#define Hh   128
#define Ll   3
#define Tt   3
#define IND  6
#define PED  8
#define EDD  4
#define OUTD 4

// GEMM tiling
#define BM 64
#define BN 128
#define BK 16
#define HS 132   // padded SMEM hidden stride (floats)

// ---------------- scratch (static device globals; no allocation) -------------
__device__ float g_h_nodes[(size_t)Nn * Hh];
__device__ float g_h_edges[(size_t)Ee * Hh];
__device__ float g_m_node[(size_t)Nn * Hh];

// ---------------- shared GEMM micro-kernels ---------------------------------
// A tile stored k-major: At[BK][BM]. All threads of a warp share the same row
// group (r constant per warp) -> A fragment loads are SMEM broadcasts.
__device__ __forceinline__ void gemm_chunk_kmajor(const float* __restrict__ At,
                                                  const float* __restrict__ Bs,
                                                  float acc[8][4], int r, int c) {
#pragma unroll
    for (int kk = 0; kk < BK; kk++) {
        const float4 a0 = *(const float4*)(At + kk * BM + r * 8);
        const float4 a1 = *(const float4*)(At + kk * BM + r * 8 + 4);
        const float4 b  = *(const float4*)(Bs + kk * BN + c * 4);
        float a[8] = {a0.x, a0.y, a0.z, a0.w, a1.x, a1.y, a1.z, a1.w};
#pragma unroll
        for (int i = 0; i < 8; i++) {
            acc[i][0] = fmaf(a[i], b.x, acc[i][0]);
            acc[i][1] = fmaf(a[i], b.y, acc[i][1]);
            acc[i][2] = fmaf(a[i], b.z, acc[i][2]);
            acc[i][3] = fmaf(a[i], b.w, acc[i][3]);
        }
    }
}

// A source = row-major hidden activations in SMEM (stride HS). Scalar loads
// are warp-broadcast (same r per warp) -> conflict-free.
__device__ __forceinline__ void gemm_chunk_rowA(const float* __restrict__ Hsm, int k0,
                                                const float* __restrict__ Bs,
                                                float acc[8][4], int r, int c) {
#pragma unroll
    for (int kk = 0; kk < BK; kk++) {
        const float4 b = *(const float4*)(Bs + kk * BN + c * 4);
        float a[8];
#pragma unroll
        for (int i = 0; i < 8; i++) a[i] = Hsm[(r * 8 + i) * HS + k0 + kk];
#pragma unroll
        for (int i = 0; i < 8; i++) {
            acc[i][0] = fmaf(a[i], b.x, acc[i][0]);
            acc[i][1] = fmaf(a[i], b.y, acc[i][1]);
            acc[i][2] = fmaf(a[i], b.z, acc[i][2]);
            acc[i][3] = fmaf(a[i], b.w, acc[i][3]);
        }
    }
}

// Copy one [BK][BN] weight chunk GMEM -> SMEM (2048 floats, 256 threads).
__device__ __forceinline__ void load_w_chunk(float* Ws, const float* __restrict__ W, int t) {
    const float4* s = (const float4*)W;
    float4* d = (float4*)Ws;
    d[t]       = s[t];
    d[t + 256] = s[t + 256];
}

__device__ __forceinline__ void zero_acc(float acc[8][4]) {
#pragma unroll
    for (int i = 0; i < 8; i++)
#pragma unroll
        for (int j = 0; j < 4; j++) acc[i][j] = 0.f;
}

// ---------------- node encoder (typed, Din=14 -> 128 -> 128) ----------------
__global__ void node_encode_kernel(const float* __restrict__ x, const float* __restrict__ pe,
                                   const float* __restrict__ W1, const float* __restrict__ b1,
                                   const float* __restrict__ W2, const float* __restrict__ b2,
                                   const int* __restrict__ node_types,
                                   float* __restrict__ h_nodes) {
    const int node = blockIdx.x;
    const int j = threadIdx.x;  // 0..127
    __shared__ float z[16];
    __shared__ float h[128];
    if (j < IND) z[j] = x[(size_t)node * IND + j];
    else if (j < IND + PED) z[j] = pe[(size_t)node * PED + (j - IND)];
    const int ty = node_types[node];
    __syncthreads();
    const float* w1 = W1 + (size_t)ty * (IND + PED) * Hh;
    float acc = b1[ty * Hh + j];
#pragma unroll
    for (int i = 0; i < IND + PED; i++) acc = fmaf(z[i], w1[i * Hh + j], acc);
    h[j] = fmaxf(acc, 0.f);
    __syncthreads();
    const float* w2 = W2 + (size_t)ty * Hh * Hh;
    float acc2 = b2[ty * Hh + j];
#pragma unroll 8
    for (int k = 0; k < Hh; k++) acc2 = fmaf(h[k], w2[k * Hh + j], acc2);
    h_nodes[(size_t)node * Hh + j] = acc2;
}

// ---------------- edge encoder (4 -> 128 -> 128), fused ----------------------
__global__ __launch_bounds__(256) void edge_encode_kernel(
    const float* __restrict__ edge_attr,
    const float* __restrict__ W1, const float* __restrict__ b1,
    const float* __restrict__ W2, const float* __restrict__ b2,
    float* __restrict__ h_edges) {
    __shared__ float s_ea[BM * EDD];
    __shared__ float s_w1[EDD * BN];
    __shared__ float Ws[BK * BN];
    __shared__ float Hsm[BM * HS];
    const int t = threadIdx.x;
    const int r = t >> 5, c = t & 31;
    const int row_base = blockIdx.x * BM;

    s_ea[t] = edge_attr[(size_t)row_base * EDD + t];
    s_w1[t] = W1[t];
    s_w1[t + 256] = W1[t + 256];
    __syncthreads();

    const float4 b1v = *(const float4*)(b1 + c * 4);
#pragma unroll
    for (int i = 0; i < 8; i++) {
        const int rr = r * 8 + i;
        float e0 = s_ea[rr * 4 + 0], e1 = s_ea[rr * 4 + 1];
        float e2 = s_ea[rr * 4 + 2], e3 = s_ea[rr * 4 + 3];
        float4 h;
        const float* bb = (const float*)&b1v;
        float hv[4];
#pragma unroll
        for (int jj = 0; jj < 4; jj++) {
            const int cc = c * 4 + jj;
            float a = bb[jj];
            a = fmaf(e0, s_w1[0 * BN + cc], a);
            a = fmaf(e1, s_w1[1 * BN + cc], a);
            a = fmaf(e2, s_w1[2 * BN + cc], a);
            a = fmaf(e3, s_w1[3 * BN + cc], a);
            hv[jj] = fmaxf(a, 0.f);
        }
        h.x = hv[0]; h.y = hv[1]; h.z = hv[2]; h.w = hv[3];
        *(float4*)(Hsm + rr * HS + c * 4) = h;
    }
    __syncthreads();

    float acc[8][4];
    zero_acc(acc);
    for (int ch = 0; ch < Hh / BK; ch++) {
        load_w_chunk(Ws, W2 + (size_t)ch * BK * BN, t);
        __syncthreads();
        gemm_chunk_rowA(Hsm, ch * BK, Ws, acc, r, c);
        __syncthreads();
    }
    const float4 b2v = *(const float4*)(b2 + c * 4);
#pragma unroll
    for (int i = 0; i < 8; i++) {
        const size_t off = (size_t)(row_base + r * 8 + i) * Hh + c * 4;
        float4 o;
        o.x = acc[i][0] + b2v.x;
        o.y = acc[i][1] + b2v.y;
        o.z = acc[i][2] + b2v.z;
        o.w = acc[i][3] + b2v.w;
        *(float4*)(h_edges + off) = o;
    }
}

// ---------------- edge update (gathered [src||dst||edge] MLP + residual) -----
__global__ __launch_bounds__(256) void edge_update_kernel(
    const float* __restrict__ h_nodes, float* __restrict__ h_edges,
    const int* __restrict__ src, const int* __restrict__ dst,
    const float* __restrict__ W1, const float* __restrict__ b1,
    const float* __restrict__ W2, const float* __restrict__ b2) {
    __shared__ float At[BK * BM];
    __shared__ float Ws[BK * BN];
    __shared__ float Hsm[BM * HS];
    __shared__ int s_src[BM];
    __shared__ int s_dst[BM];
    const int t = threadIdx.x;
    const int r = t >> 5, c = t & 31;
    const int row_base = blockIdx.x * BM;
    const int lrow = t & 63, kq = t >> 6;

    if (t < BM) s_src[t] = src[row_base + t];
    else if (t < 2 * BM) s_dst[t - BM] = dst[row_base + t - BM];
    __syncthreads();

    float acc[8][4];
    zero_acc(acc);

    // stage 1: hidden = relu(A[64,384] @ W1 + b1), A gathered on the fly
    for (int ch = 0; ch < 3 * Hh / BK; ch++) {
        const int k0 = ch * BK;
        const float* base;
        int k0c;
        if (k0 < Hh)           { base = h_nodes + (size_t)s_src[lrow] * Hh;      k0c = k0; }
        else if (k0 < 2 * Hh)  { base = h_nodes + (size_t)s_dst[lrow] * Hh;      k0c = k0 - Hh; }
        else                   { base = h_edges + (size_t)(row_base + lrow) * Hh; k0c = k0 - 2 * Hh; }
        const float4 v = *(const float4*)(base + k0c + kq * 4);
        At[(kq * 4 + 0) * BM + lrow] = v.x;
        At[(kq * 4 + 1) * BM + lrow] = v.y;
        At[(kq * 4 + 2) * BM + lrow] = v.z;
        At[(kq * 4 + 3) * BM + lrow] = v.w;
        load_w_chunk(Ws, W1 + (size_t)k0 * BN, t);
        __syncthreads();
        gemm_chunk_kmajor(At, Ws, acc, r, c);
        __syncthreads();
    }
    const float4 b1v = *(const float4*)(b1 + c * 4);
#pragma unroll
    for (int i = 0; i < 8; i++) {
        float4 h;
        h.x = fmaxf(acc[i][0] + b1v.x, 0.f);
        h.y = fmaxf(acc[i][1] + b1v.y, 0.f);
        h.z = fmaxf(acc[i][2] + b1v.z, 0.f);
        h.w = fmaxf(acc[i][3] + b1v.w, 0.f);
        *(float4*)(Hsm + (r * 8 + i) * HS + c * 4) = h;
    }
    zero_acc(acc);
    __syncthreads();

    // stage 2: out = hidden @ W2 + b2 + residual
    for (int ch = 0; ch < Hh / BK; ch++) {
        load_w_chunk(Ws, W2 + (size_t)ch * BK * BN, t);
        __syncthreads();
        gemm_chunk_rowA(Hsm, ch * BK, Ws, acc, r, c);
        __syncthreads();
    }
    const float4 b2v = *(const float4*)(b2 + c * 4);
#pragma unroll
    for (int i = 0; i < 8; i++) {
        const size_t off = (size_t)(row_base + r * 8 + i) * Hh + c * 4;
        const float4 res = *(const float4*)(h_edges + off);
        float4 o;
        o.x = acc[i][0] + b2v.x + res.x;
        o.y = acc[i][1] + b2v.y + res.y;
        o.z = acc[i][2] + b2v.z + res.z;
        o.w = acc[i][3] + b2v.w + res.w;
        *(float4*)(h_edges + off) = o;
    }
}

// ---------------- scatter-add aggregation ------------------------------------
__global__ void zero_kernel(float* __restrict__ p, int n) {
    const int i = blockIdx.x * blockDim.x + threadIdx.x;
    if (i < n) p[i] = 0.f;
}

__global__ void scatter_kernel(const float* __restrict__ h_edges,
                               const int* __restrict__ dst,
                               float* __restrict__ m_node) {
    const int idx = blockIdx.x * blockDim.x + threadIdx.x;
    const int e = idx >> 7;
    const int j = idx & 127;
    atomicAdd(m_node + (size_t)dst[e] * Hh + j, h_edges[idx]);
}

// ---------------- node update + fusion (4 GEMM stages fused) -----------------
__global__ __launch_bounds__(256) void node_update_kernel(
    float* __restrict__ h_nodes, const float* __restrict__ m_node,
    const float* __restrict__ nuW1, const float* __restrict__ nub1,
    const float* __restrict__ nuW2, const float* __restrict__ nub2,
    const float* __restrict__ fuW1, const float* __restrict__ fub1,
    const float* __restrict__ fuW2, const float* __restrict__ fub2) {
    __shared__ float At[BK * BM];
    __shared__ float Ws[BK * BN];
    __shared__ float Hsm[BM * HS];
    const int t = threadIdx.x;
    const int r = t >> 5, c = t & 31;
    const int row_base = blockIdx.x * BM;
    const int lrow = t & 63, kq = t >> 6;
    const int gload = min(row_base + lrow, Nn - 1);

    float acc[8][4];
    zero_acc(acc);

    // S1: hidden = relu([h_nodes || m_node] @ nuW1 + b1)
    for (int ch = 0; ch < 2 * Hh / BK; ch++) {
        const int k0 = ch * BK;
        const float* base = (k0 < Hh) ? h_nodes : m_node;
        const int k0c = k0 & (Hh - 1);
        const float4 v = *(const float4*)(base + (size_t)gload * Hh + k0c + kq * 4);
        At[(kq * 4 + 0) * BM + lrow] = v.x;
        At[(kq * 4 + 1) * BM + lrow] = v.y;
        At[(kq * 4 + 2) * BM + lrow] = v.z;
        At[(kq * 4 + 3) * BM + lrow] = v.w;
        load_w_chunk(Ws, nuW1 + (size_t)k0 * BN, t);
        __syncthreads();
        gemm_chunk_kmajor(At, Ws, acc, r, c);
        __syncthreads();
    }
    {
        const float4 bv = *(const float4*)(nub1 + c * 4);
#pragma unroll
        for (int i = 0; i < 8; i++) {
            float4 h;
            h.x = fmaxf(acc[i][0] + bv.x, 0.f);
            h.y = fmaxf(acc[i][1] + bv.y, 0.f);
            h.z = fmaxf(acc[i][2] + bv.z, 0.f);
            h.w = fmaxf(acc[i][3] + bv.w, 0.f);
            *(float4*)(Hsm + (r * 8 + i) * HS + c * 4) = h;
        }
    }
    zero_acc(acc);
    __syncthreads();

    // S2: local = hidden @ nuW2 + b2 + h_nodes (residual)
    for (int ch = 0; ch < Hh / BK; ch++) {
        load_w_chunk(Ws, nuW2 + (size_t)ch * BK * BN, t);
        __syncthreads();
        gemm_chunk_rowA(Hsm, ch * BK, Ws, acc, r, c);
        __syncthreads();
    }
    {
        const float4 bv = *(const float4*)(nub2 + c * 4);
#pragma unroll
        for (int i = 0; i < 8; i++) {
            const int g = min(row_base + r * 8 + i, Nn - 1);
            const float4 res = *(const float4*)(h_nodes + (size_t)g * Hh + c * 4);
            float4 lv;
            lv.x = acc[i][0] + bv.x + res.x;
            lv.y = acc[i][1] + bv.y + res.y;
            lv.z = acc[i][2] + bv.z + res.z;
            lv.w = acc[i][3] + bv.w + res.w;
            *(float4*)(Hsm + (r * 8 + i) * HS + c * 4) = lv;   // safe: all Hsm reads done
        }
    }
    zero_acc(acc);
    __syncthreads();

    // S3: t1 = relu(local @ fuW1 + b1)
    for (int ch = 0; ch < Hh / BK; ch++) {
        load_w_chunk(Ws, fuW1 + (size_t)ch * BK * BN, t);
        __syncthreads();
        gemm_chunk_rowA(Hsm, ch * BK, Ws, acc, r, c);
        __syncthreads();
    }
    {
        const float4 bv = *(const float4*)(fub1 + c * 4);
#pragma unroll
        for (int i = 0; i < 8; i++) {
            float4 h;
            h.x = fmaxf(acc[i][0] + bv.x, 0.f);
            h.y = fmaxf(acc[i][1] + bv.y, 0.f);
            h.z = fmaxf(acc[i][2] + bv.z, 0.f);
            h.w = fmaxf(acc[i][3] + bv.w, 0.f);
            *(float4*)(Hsm + (r * 8 + i) * HS + c * 4) = h;
        }
    }
    zero_acc(acc);
    __syncthreads();

    // S4: h_nodes = t1 @ fuW2 + b2
    for (int ch = 0; ch < Hh / BK; ch++) {
        load_w_chunk(Ws, fuW2 + (size_t)ch * BK * BN, t);
        __syncthreads();
        gemm_chunk_rowA(Hsm, ch * BK, Ws, acc, r, c);
        __syncthreads();
    }
    {
        const float4 bv = *(const float4*)(fub2 + c * 4);
#pragma unroll
        for (int i = 0; i < 8; i++) {
            const int g = row_base + r * 8 + i;
            if (g < Nn) {
                float4 o;
                o.x = acc[i][0] + bv.x;
                o.y = acc[i][1] + bv.y;
                o.z = acc[i][2] + bv.z;
                o.w = acc[i][3] + bv.w;
                *(float4*)(h_nodes + (size_t)g * Hh + c * 4) = o;
            }
        }
    }
}

// ---------------- typed decoder (128 -> 128 -> 4) ----------------------------
__global__ void decode_kernel(const float* __restrict__ h_nodes,
                              const float* __restrict__ W1, const float* __restrict__ b1,
                              const float* __restrict__ W2, const float* __restrict__ b2,
                              const int* __restrict__ node_types,
                              float* __restrict__ out) {
    const int node = blockIdx.x;
    const int t = threadIdx.x;  // 128
    __shared__ float hin[128];
    __shared__ float h[128];
    hin[t] = h_nodes[(size_t)node * Hh + t];
    const int ty = node_types[node];
    __syncthreads();
    const float* w1 = W1 + (size_t)ty * Hh * Hh;
    float acc = b1[ty * Hh + t];
#pragma unroll 8
    for (int k = 0; k < Hh; k++) acc = fmaf(hin[k], w1[k * Hh + t], acc);
    h[t] = fmaxf(acc, 0.f);
    __syncthreads();
    const int o = t >> 5, lane = t & 31;
    const float* w2 = W2 + (size_t)ty * Hh * OUTD;
    float s = 0.f;
#pragma unroll
    for (int k = lane; k < Hh; k += 32) s = fmaf(h[k], w2[k * OUTD + o], s);
#pragma unroll
    for (int off = 16; off; off >>= 1) s += __shfl_down_sync(0xffffffffu, s, off);
    if (lane == 0) out[(size_t)node * OUTD + o] = s + b2[ty * OUTD + o];
}

// ---------------- launch ------------------------------------------------------
extern "C" void kernel_launch(void* const* d_in, const int* in_sizes, int n_in,
                              void* d_out, int out_size) {
    const float* x        = (const float*)d_in[0];
    const float* pe       = (const float*)d_in[1];
    const float* edge_attr= (const float*)d_in[2];
    const float* enc_W1   = (const float*)d_in[3];
    const float* enc_b1   = (const float*)d_in[4];
    const float* enc_W2   = (const float*)d_in[5];
    const float* enc_b2   = (const float*)d_in[6];
    const float* ee_W1    = (const float*)d_in[7];
    const float* ee_b1    = (const float*)d_in[8];
    const float* ee_W2    = (const float*)d_in[9];
    const float* ee_b2    = (const float*)d_in[10];
    const float* eu_W1    = (const float*)d_in[11];
    const float* eu_b1    = (const float*)d_in[12];
    const float* eu_W2    = (const float*)d_in[13];
    const float* eu_b2    = (const float*)d_in[14];
    const float* nu_W1    = (const float*)d_in[15];
    const float* nu_b1    = (const float*)d_in[16];
    const float* nu_W2    = (const float*)d_in[17];
    const float* nu_b2    = (const float*)d_in[18];
    const float* fu_W1    = (const float*)d_in[19];
    const float* fu_b1    = (const float*)d_in[20];
    const float* fu_W2    = (const float*)d_in[21];
    const float* fu_b2    = (const float*)d_in[22];
    const float* dec_W1   = (const float*)d_in[23];
    const float* dec_b1   = (const float*)d_in[24];
    const float* dec_W2   = (const float*)d_in[25];
    const float* dec_b2   = (const float*)d_in[26];
    const int*   edge_index = (const int*)d_in[27];
    const int*   node_types = (const int*)d_in[28];
    float* out = (float*)d_out;

    float *h_nodes, *h_edges, *m_node;
    cudaGetSymbolAddress((void**)&h_nodes, g_h_nodes);
    cudaGetSymbolAddress((void**)&h_edges, g_h_edges);
    cudaGetSymbolAddress((void**)&m_node, g_m_node);

    const int* srcp = edge_index;
    const int* dstp = edge_index + Ee;

    node_encode_kernel<<<Nn, 128>>>(x, pe, enc_W1, enc_b1, enc_W2, enc_b2,
                                    node_types, h_nodes);
    edge_encode_kernel<<<Ee / BM, 256>>>(edge_attr, ee_W1, ee_b1, ee_W2, ee_b2, h_edges);

    for (int l = 0; l < Ll; l++) {
        edge_update_kernel<<<Ee / BM, 256>>>(
            h_nodes, h_edges, srcp, dstp,
            eu_W1 + (size_t)l * 3 * Hh * Hh, eu_b1 + (size_t)l * Hh,
            eu_W2 + (size_t)l * Hh * Hh,     eu_b2 + (size_t)l * Hh);
        zero_kernel<<<(Nn * Hh + 255) / 256, 256>>>(m_node, Nn * Hh);
        scatter_kernel<<<(Ee * Hh) / 256, 256>>>(h_edges, dstp, m_node);
        node_update_kernel<<<(Nn + BM - 1) / BM, 256>>>(
            h_nodes, m_node,
            nu_W1 + (size_t)l * 2 * Hh * Hh, nu_b1 + (size_t)l * Hh,
            nu_W2 + (size_t)l * Hh * Hh,     nu_b2 + (size_t)l * Hh,
            fu_W1 + (size_t)l * Hh * Hh,     fu_b1 + (size_t)l * Hh,
            fu_W2 + (size_t)l * Hh * Hh,     fu_b2 + (size_t)l * Hh);
    }

    decode_kernel<<<Nn, 128>>>(h_nodes, dec_W1, dec_b1, dec_W2, dec_b2,
                               node_types, out);
}

// round 7
// speedup vs baseline: 1.5974x; 1.5974x over previous
#include <cuda_runtime.h>

// Problem sizes (fixed by the reference)
#define Nn   20000
#define Ee   320000
#define Hh   128
#define Ll   3
#define Tt   3
#define IND  6
#define PED  8
#define EDD  4
#define OUTD 4

// GEMM tiling
#define BM 64
#define BN 128
#define BK 16
#define HS 132   // padded SMEM hidden stride (floats)

// ---------------- scratch (static device globals; no allocation) -------------
__device__ float g_h_nodes[(size_t)Nn * Hh];
__device__ float g_h_edges[(size_t)Ee * Hh];
__device__ float g_m_node[(size_t)Nn * Hh];

// ---------------- shared GEMM micro-kernels ---------------------------------
// A tile stored k-major: At[BK][BM]. All threads of a warp share the same row
// group (r constant per warp) -> A fragment loads are SMEM broadcasts.
__device__ __forceinline__ void gemm_chunk_kmajor(const float* __restrict__ At,
                                                  const float* __restrict__ Bs,
                                                  float acc[8][4], int r, int c) {
#pragma unroll
    for (int kk = 0; kk < BK; kk++) {
        const float4 a0 = *(const float4*)(At + kk * BM + r * 8);
        const float4 a1 = *(const float4*)(At + kk * BM + r * 8 + 4);
        const float4 b  = *(const float4*)(Bs + kk * BN + c * 4);
        float a[8] = {a0.x, a0.y, a0.z, a0.w, a1.x, a1.y, a1.z, a1.w};
#pragma unroll
        for (int i = 0; i < 8; i++) {
            acc[i][0] = fmaf(a[i], b.x, acc[i][0]);
            acc[i][1] = fmaf(a[i], b.y, acc[i][1]);
            acc[i][2] = fmaf(a[i], b.z, acc[i][2]);
            acc[i][3] = fmaf(a[i], b.w, acc[i][3]);
        }
    }
}

// A source = row-major hidden activations in SMEM (stride HS). Scalar loads
// are warp-broadcast (same r per warp) -> conflict-free.
__device__ __forceinline__ void gemm_chunk_rowA(const float* __restrict__ Hsm, int k0,
                                                const float* __restrict__ Bs,
                                                float acc[8][4], int r, int c) {
#pragma unroll
    for (int kk = 0; kk < BK; kk++) {
        const float4 b = *(const float4*)(Bs + kk * BN + c * 4);
        float a[8];
#pragma unroll
        for (int i = 0; i < 8; i++) a[i] = Hsm[(r * 8 + i) * HS + k0 + kk];
#pragma unroll
        for (int i = 0; i < 8; i++) {
            acc[i][0] = fmaf(a[i], b.x, acc[i][0]);
            acc[i][1] = fmaf(a[i], b.y, acc[i][1]);
            acc[i][2] = fmaf(a[i], b.z, acc[i][2]);
            acc[i][3] = fmaf(a[i], b.w, acc[i][3]);
        }
    }
}

// Copy one [BK][BN] weight chunk GMEM -> SMEM (2048 floats, 256 threads).
__device__ __forceinline__ void load_w_chunk(float* Ws, const float* __restrict__ W, int t) {
    const float4* s = (const float4*)W;
    float4* d = (float4*)Ws;
    d[t]       = s[t];
    d[t + 256] = s[t + 256];
}

__device__ __forceinline__ void zero_acc(float acc[8][4]) {
#pragma unroll
    for (int i = 0; i < 8; i++)
#pragma unroll
        for (int j = 0; j < 4; j++) acc[i][j] = 0.f;
}

// ---------------- node encoder (typed, Din=14 -> 128 -> 128) ----------------
__global__ void node_encode_kernel(const float* __restrict__ x, const float* __restrict__ pe,
                                   const float* __restrict__ W1, const float* __restrict__ b1,
                                   const float* __restrict__ W2, const float* __restrict__ b2,
                                   const int* __restrict__ node_types,
                                   float* __restrict__ h_nodes) {
    const int node = blockIdx.x;
    const int j = threadIdx.x;  // 0..127
    __shared__ float z[16];
    __shared__ float h[128];
    if (j < IND) z[j] = x[(size_t)node * IND + j];
    else if (j < IND + PED) z[j] = pe[(size_t)node * PED + (j - IND)];
    const int ty = node_types[node];
    __syncthreads();
    const float* w1 = W1 + (size_t)ty * (IND + PED) * Hh;
    float acc = b1[ty * Hh + j];
#pragma unroll
    for (int i = 0; i < IND + PED; i++) acc = fmaf(z[i], w1[i * Hh + j], acc);
    h[j] = fmaxf(acc, 0.f);
    __syncthreads();
    const float* w2 = W2 + (size_t)ty * Hh * Hh;
    float acc2 = b2[ty * Hh + j];
#pragma unroll 8
    for (int k = 0; k < Hh; k++) acc2 = fmaf(h[k], w2[k * Hh + j], acc2);
    h_nodes[(size_t)node * Hh + j] = acc2;
}

// ---------------- edge encoder (4 -> 128 -> 128), fused ----------------------
__global__ __launch_bounds__(256) void edge_encode_kernel(
    const float* __restrict__ edge_attr,
    const float* __restrict__ W1, const float* __restrict__ b1,
    const float* __restrict__ W2, const float* __restrict__ b2,
    float* __restrict__ h_edges) {
    __shared__ float s_ea[BM * EDD];
    __shared__ float s_w1[EDD * BN];
    __shared__ float Ws[BK * BN];
    __shared__ float Hsm[BM * HS];
    const int t = threadIdx.x;
    const int r = t >> 5, c = t & 31;
    const int row_base = blockIdx.x * BM;

    s_ea[t] = edge_attr[(size_t)row_base * EDD + t];
    s_w1[t] = W1[t];
    s_w1[t + 256] = W1[t + 256];
    __syncthreads();

    const float4 b1v = *(const float4*)(b1 + c * 4);
#pragma unroll
    for (int i = 0; i < 8; i++) {
        const int rr = r * 8 + i;
        float e0 = s_ea[rr * 4 + 0], e1 = s_ea[rr * 4 + 1];
        float e2 = s_ea[rr * 4 + 2], e3 = s_ea[rr * 4 + 3];
        float4 h;
        const float* bb = (const float*)&b1v;
        float hv[4];
#pragma unroll
        for (int jj = 0; jj < 4; jj++) {
            const int cc = c * 4 + jj;
            float a = bb[jj];
            a = fmaf(e0, s_w1[0 * BN + cc], a);
            a = fmaf(e1, s_w1[1 * BN + cc], a);
            a = fmaf(e2, s_w1[2 * BN + cc], a);
            a = fmaf(e3, s_w1[3 * BN + cc], a);
            hv[jj] = fmaxf(a, 0.f);
        }
        h.x = hv[0]; h.y = hv[1]; h.z = hv[2]; h.w = hv[3];
        *(float4*)(Hsm + rr * HS + c * 4) = h;
    }
    __syncthreads();

    float acc[8][4];
    zero_acc(acc);
    for (int ch = 0; ch < Hh / BK; ch++) {
        load_w_chunk(Ws, W2 + (size_t)ch * BK * BN, t);
        __syncthreads();
        gemm_chunk_rowA(Hsm, ch * BK, Ws, acc, r, c);
        __syncthreads();
    }
    const float4 b2v = *(const float4*)(b2 + c * 4);
#pragma unroll
    for (int i = 0; i < 8; i++) {
        const size_t off = (size_t)(row_base + r * 8 + i) * Hh + c * 4;
        float4 o;
        o.x = acc[i][0] + b2v.x;
        o.y = acc[i][1] + b2v.y;
        o.z = acc[i][2] + b2v.z;
        o.w = acc[i][3] + b2v.w;
        *(float4*)(h_edges + off) = o;
    }
}

// ---------------- edge update (gathered [src||dst||edge] MLP + residual) -----
__global__ __launch_bounds__(256) void edge_update_kernel(
    const float* __restrict__ h_nodes, float* __restrict__ h_edges,
    const int* __restrict__ src, const int* __restrict__ dst,
    const float* __restrict__ W1, const float* __restrict__ b1,
    const float* __restrict__ W2, const float* __restrict__ b2) {
    __shared__ float At[BK * BM];
    __shared__ float Ws[BK * BN];
    __shared__ float Hsm[BM * HS];
    __shared__ int s_src[BM];
    __shared__ int s_dst[BM];
    const int t = threadIdx.x;
    const int r = t >> 5, c = t & 31;
    const int row_base = blockIdx.x * BM;
    const int lrow = t & 63, kq = t >> 6;

    if (t < BM) s_src[t] = src[row_base + t];
    else if (t < 2 * BM) s_dst[t - BM] = dst[row_base + t - BM];
    __syncthreads();

    float acc[8][4];
    zero_acc(acc);

    // stage 1: hidden = relu(A[64,384] @ W1 + b1), A gathered on the fly
    for (int ch = 0; ch < 3 * Hh / BK; ch++) {
        const int k0 = ch * BK;
        const float* base;
        int k0c;
        if (k0 < Hh)           { base = h_nodes + (size_t)s_src[lrow] * Hh;      k0c = k0; }
        else if (k0 < 2 * Hh)  { base = h_nodes + (size_t)s_dst[lrow] * Hh;      k0c = k0 - Hh; }
        else                   { base = h_edges + (size_t)(row_base + lrow) * Hh; k0c = k0 - 2 * Hh; }
        const float4 v = *(const float4*)(base + k0c + kq * 4);
        At[(kq * 4 + 0) * BM + lrow] = v.x;
        At[(kq * 4 + 1) * BM + lrow] = v.y;
        At[(kq * 4 + 2) * BM + lrow] = v.z;
        At[(kq * 4 + 3) * BM + lrow] = v.w;
        load_w_chunk(Ws, W1 + (size_t)k0 * BN, t);
        __syncthreads();
        gemm_chunk_kmajor(At, Ws, acc, r, c);
        __syncthreads();
    }
    const float4 b1v = *(const float4*)(b1 + c * 4);
#pragma unroll
    for (int i = 0; i < 8; i++) {
        float4 h;
        h.x = fmaxf(acc[i][0] + b1v.x, 0.f);
        h.y = fmaxf(acc[i][1] + b1v.y, 0.f);
        h.z = fmaxf(acc[i][2] + b1v.z, 0.f);
        h.w = fmaxf(acc[i][3] + b1v.w, 0.f);
        *(float4*)(Hsm + (r * 8 + i) * HS + c * 4) = h;
    }
    zero_acc(acc);
    __syncthreads();

    // stage 2: out = hidden @ W2 + b2 + residual
    for (int ch = 0; ch < Hh / BK; ch++) {
        load_w_chunk(Ws, W2 + (size_t)ch * BK * BN, t);
        __syncthreads();
        gemm_chunk_rowA(Hsm, ch * BK, Ws, acc, r, c);
        __syncthreads();
    }
    const float4 b2v = *(const float4*)(b2 + c * 4);
#pragma unroll
    for (int i = 0; i < 8; i++) {
        const size_t off = (size_t)(row_base + r * 8 + i) * Hh + c * 4;
        const float4 res = *(const float4*)(h_edges + off);
        float4 o;
        o.x = acc[i][0] + b2v.x + res.x;
        o.y = acc[i][1] + b2v.y + res.y;
        o.z = acc[i][2] + b2v.z + res.z;
        o.w = acc[i][3] + b2v.w + res.w;
        *(float4*)(h_edges + off) = o;
    }
}

// ---------------- scatter-add aggregation ------------------------------------
__global__ void zero_kernel(float* __restrict__ p, int n) {
    const int i = blockIdx.x * blockDim.x + threadIdx.x;
    if (i < n) p[i] = 0.f;
}

__global__ void scatter_kernel(const float* __restrict__ h_edges,
                               const int* __restrict__ dst,
                               float* __restrict__ m_node) {
    const int idx = blockIdx.x * blockDim.x + threadIdx.x;
    const int e = idx >> 7;
    const int j = idx & 127;
    atomicAdd(m_node + (size_t)dst[e] * Hh + j, h_edges[idx]);
}

// ---------------- node update + fusion (4 GEMM stages fused) -----------------
__global__ __launch_bounds__(256) void node_update_kernel(
    float* __restrict__ h_nodes, const float* __restrict__ m_node,
    const float* __restrict__ nuW1, const float* __restrict__ nub1,
    const float* __restrict__ nuW2, const float* __restrict__ nub2,
    const float* __restrict__ fuW1, const float* __restrict__ fub1,
    const float* __restrict__ fuW2, const float* __restrict__ fub2) {
    __shared__ float At[BK * BM];
    __shared__ float Ws[BK * BN];
    __shared__ float Hsm[BM * HS];
    const int t = threadIdx.x;
    const int r = t >> 5, c = t & 31;
    const int row_base = blockIdx.x * BM;
    const int lrow = t & 63, kq = t >> 6;
    const int gload = min(row_base + lrow, Nn - 1);

    float acc[8][4];
    zero_acc(acc);

    // S1: hidden = relu([h_nodes || m_node] @ nuW1 + b1)
    for (int ch = 0; ch < 2 * Hh / BK; ch++) {
        const int k0 = ch * BK;
        const float* base = (k0 < Hh) ? h_nodes : m_node;
        const int k0c = k0 & (Hh - 1);
        const float4 v = *(const float4*)(base + (size_t)gload * Hh + k0c + kq * 4);
        At[(kq * 4 + 0) * BM + lrow] = v.x;
        At[(kq * 4 + 1) * BM + lrow] = v.y;
        At[(kq * 4 + 2) * BM + lrow] = v.z;
        At[(kq * 4 + 3) * BM + lrow] = v.w;
        load_w_chunk(Ws, nuW1 + (size_t)k0 * BN, t);
        __syncthreads();
        gemm_chunk_kmajor(At, Ws, acc, r, c);
        __syncthreads();
    }
    {
        const float4 bv = *(const float4*)(nub1 + c * 4);
#pragma unroll
        for (int i = 0; i < 8; i++) {
            float4 h;
            h.x = fmaxf(acc[i][0] + bv.x, 0.f);
            h.y = fmaxf(acc[i][1] + bv.y, 0.f);
            h.z = fmaxf(acc[i][2] + bv.z, 0.f);
            h.w = fmaxf(acc[i][3] + bv.w, 0.f);
            *(float4*)(Hsm + (r * 8 + i) * HS + c * 4) = h;
        }
    }
    zero_acc(acc);
    __syncthreads();

    // S2: local = hidden @ nuW2 + b2 + h_nodes (residual)
    for (int ch = 0; ch < Hh / BK; ch++) {
        load_w_chunk(Ws, nuW2 + (size_t)ch * BK * BN, t);
        __syncthreads();
        gemm_chunk_rowA(Hsm, ch * BK, Ws, acc, r, c);
        __syncthreads();
    }
    {
        const float4 bv = *(const float4*)(nub2 + c * 4);
#pragma unroll
        for (int i = 0; i < 8; i++) {
            const int g = min(row_base + r * 8 + i, Nn - 1);
            const float4 res = *(const float4*)(h_nodes + (size_t)g * Hh + c * 4);
            float4 lv;
            lv.x = acc[i][0] + bv.x + res.x;
            lv.y = acc[i][1] + bv.y + res.y;
            lv.z = acc[i][2] + bv.z + res.z;
            lv.w = acc[i][3] + bv.w + res.w;
            *(float4*)(Hsm + (r * 8 + i) * HS + c * 4) = lv;   // safe: all Hsm reads done
        }
    }
    zero_acc(acc);
    __syncthreads();

    // S3: t1 = relu(local @ fuW1 + b1)
    for (int ch = 0; ch < Hh / BK; ch++) {
        load_w_chunk(Ws, fuW1 + (size_t)ch * BK * BN, t);
        __syncthreads();
        gemm_chunk_rowA(Hsm, ch * BK, Ws, acc, r, c);
        __syncthreads();
    }
    {
        const float4 bv = *(const float4*)(fub1 + c * 4);
#pragma unroll
        for (int i = 0; i < 8; i++) {
            float4 h;
            h.x = fmaxf(acc[i][0] + bv.x, 0.f);
            h.y = fmaxf(acc[i][1] + bv.y, 0.f);
            h.z = fmaxf(acc[i][2] + bv.z, 0.f);
            h.w = fmaxf(acc[i][3] + bv.w, 0.f);
            *(float4*)(Hsm + (r * 8 + i) * HS + c * 4) = h;
        }
    }
    zero_acc(acc);
    __syncthreads();

    // S4: h_nodes = t1 @ fuW2 + b2
    for (int ch = 0; ch < Hh / BK; ch++) {
        load_w_chunk(Ws, fuW2 + (size_t)ch * BK * BN, t);
        __syncthreads();
        gemm_chunk_rowA(Hsm, ch * BK, Ws, acc, r, c);
        __syncthreads();
    }
    {
        const float4 bv = *(const float4*)(fub2 + c * 4);
#pragma unroll
        for (int i = 0; i < 8; i++) {
            const int g = row_base + r * 8 + i;
            if (g < Nn) {
                float4 o;
                o.x = acc[i][0] + bv.x;
                o.y = acc[i][1] + bv.y;
                o.z = acc[i][2] + bv.z;
                o.w = acc[i][3] + bv.w;
                *(float4*)(h_nodes + (size_t)g * Hh + c * 4) = o;
            }
        }
    }
}

// ---------------- typed decoder (128 -> 128 -> 4) ----------------------------
__global__ void decode_kernel(const float* __restrict__ h_nodes,
                              const float* __restrict__ W1, const float* __restrict__ b1,
                              const float* __restrict__ W2, const float* __restrict__ b2,
                              const int* __restrict__ node_types,
                              float* __restrict__ out) {
    const int node = blockIdx.x;
    const int t = threadIdx.x;  // 128
    __shared__ float hin[128];
    __shared__ float h[128];
    hin[t] = h_nodes[(size_t)node * Hh + t];
    const int ty = node_types[node];
    __syncthreads();
    const float* w1 = W1 + (size_t)ty * Hh * Hh;
    float acc = b1[ty * Hh + t];
#pragma unroll 8
    for (int k = 0; k < Hh; k++) acc = fmaf(hin[k], w1[k * Hh + t], acc);
    h[t] = fmaxf(acc, 0.f);
    __syncthreads();
    const int o = t >> 5, lane = t & 31;
    const float* w2 = W2 + (size_t)ty * Hh * OUTD;
    float s = 0.f;
#pragma unroll
    for (int k = lane; k < Hh; k += 32) s = fmaf(h[k], w2[k * OUTD + o], s);
#pragma unroll
    for (int off = 16; off; off >>= 1) s += __shfl_down_sync(0xffffffffu, s, off);
    if (lane == 0) out[(size_t)node * OUTD + o] = s + b2[ty * OUTD + o];
}

// ---------------- launch ------------------------------------------------------
extern "C" void kernel_launch(void* const* d_in, const int* in_sizes, int n_in,
                              void* d_out, int out_size) {
    const float* x        = (const float*)d_in[0];
    const float* pe       = (const float*)d_in[1];
    const float* edge_attr= (const float*)d_in[2];
    const float* enc_W1   = (const float*)d_in[3];
    const float* enc_b1   = (const float*)d_in[4];
    const float* enc_W2   = (const float*)d_in[5];
    const float* enc_b2   = (const float*)d_in[6];
    const float* ee_W1    = (const float*)d_in[7];
    const float* ee_b1    = (const float*)d_in[8];
    const float* ee_W2    = (const float*)d_in[9];
    const float* ee_b2    = (const float*)d_in[10];
    const float* eu_W1    = (const float*)d_in[11];
    const float* eu_b1    = (const float*)d_in[12];
    const float* eu_W2    = (const float*)d_in[13];
    const float* eu_b2    = (const float*)d_in[14];
    const float* nu_W1    = (const float*)d_in[15];
    const float* nu_b1    = (const float*)d_in[16];
    const float* nu_W2    = (const float*)d_in[17];
    const float* nu_b2    = (const float*)d_in[18];
    const float* fu_W1    = (const float*)d_in[19];
    const float* fu_b1    = (const float*)d_in[20];
    const float* fu_W2    = (const float*)d_in[21];
    const float* fu_b2    = (const float*)d_in[22];
    const float* dec_W1   = (const float*)d_in[23];
    const float* dec_b1   = (const float*)d_in[24];
    const float* dec_W2   = (const float*)d_in[25];
    const float* dec_b2   = (const float*)d_in[26];
    const int*   edge_index = (const int*)d_in[27];
    const int*   node_types = (const int*)d_in[28];
    float* out = (float*)d_out;

    float *h_nodes, *h_edges, *m_node;
    cudaGetSymbolAddress((void**)&h_nodes, g_h_nodes);
    cudaGetSymbolAddress((void**)&h_edges, g_h_edges);
    cudaGetSymbolAddress((void**)&m_node, g_m_node);

    const int* srcp = edge_index;
    const int* dstp = edge_index + Ee;

    node_encode_kernel<<<Nn, 128>>>(x, pe, enc_W1, enc_b1, enc_W2, enc_b2,
                                    node_types, h_nodes);
    edge_encode_kernel<<<Ee / BM, 256>>>(edge_attr, ee_W1, ee_b1, ee_W2, ee_b2, h_edges);

    for (int l = 0; l < Ll; l++) {
        edge_update_kernel<<<Ee / BM, 256>>>(
            h_nodes, h_edges, srcp, dstp,
            eu_W1 + (size_t)l * 3 * Hh * Hh, eu_b1 + (size_t)l * Hh,
            eu_W2 + (size_t)l * Hh * Hh,     eu_b2 + (size_t)l * Hh);
        zero_kernel<<<(Nn * Hh + 255) / 256, 256>>>(m_node, Nn * Hh);
        scatter_kernel<<<(Ee * Hh) / 256, 256>>>(h_edges, dstp, m_node);
        node_update_kernel<<<(Nn + BM - 1) / BM, 256>>>(
            h_nodes, m_node,
            nu_W1 + (size_t)l * 2 * Hh * Hh, nu_b1 + (size_t)l * Hh,
            nu_W2 + (size_t)l * Hh * Hh,     nu_b2 + (size_t)l * Hh,
            fu_W1 + (size_t)l * Hh * Hh,     fu_b1 + (size_t)l * Hh,
            fu_W2 + (size_t)l * Hh * Hh,     fu_b2 + (size_t)l * Hh);
    }

    decode_kernel<<<Nn, 128>>>(h_nodes, dec_W1, dec_b1, dec_W2, dec_b2,
                               node_types, out);
}